// round 15
// baseline (speedup 1.0000x reference)
#include <cuda_runtime.h>
#include <cuda_fp16.h>
#include <cstdint>
#include <cstddef>

#define BB 4
#define TT 4096
#define CC 1024
#define HH 16
#define GG 8
#define HSD 64
#define GTT 512

// ---- scratch (static device globals; no runtime allocation allowed) ----
__device__ __align__(16) __half g_qkvh[(size_t)BB*TT*3*CC];   // fp16 qkv (96MB)
__device__ __align__(16) __half g_qh[(size_t)BB*HH*GG*GTT*HSD];
__device__ __align__(16) __half g_kh[(size_t)BB*HH*GG*GTT*HSD];
__device__ __align__(16) __half g_vh[(size_t)BB*HH*GG*GTT*HSD];
__device__ __align__(16) __half g_xh[(size_t)BB*TT*CC];
__device__ __align__(16) __half g_wqh[(size_t)CC*3*CC];
__device__ __align__(16) __half g_woh[(size_t)CC*CC];
__device__ __align__(16) __half g_obh[(size_t)BB*TT*CC];

// =================== small helpers ===================
__device__ __forceinline__ uint32_t packh(float lo, float hi) {
    uint32_t r;
    asm("cvt.rn.f16x2.f32 %0,%1,%2;" : "=r"(r) : "f"(hi), "f"(lo));
    return r;
}
__device__ __forceinline__ void cp16(void* s, const void* g) {
    uint32_t sa = (uint32_t)__cvta_generic_to_shared(s);
    asm volatile("cp.async.cg.shared.global [%0], [%1], 16;" :: "r"(sa), "l"(g));
}
__device__ __forceinline__ void cp16s(uint32_t sa, const void* g) {
    asm volatile("cp.async.cg.shared.global [%0], [%1], 16;" :: "r"(sa), "l"(g));
}
__device__ __forceinline__ void ldsm4(uint32_t* r, uint32_t a) {
    asm volatile("ldmatrix.sync.aligned.m8n8.x4.shared.b16 {%0,%1,%2,%3},[%4];"
        : "=r"(r[0]), "=r"(r[1]), "=r"(r[2]), "=r"(r[3]) : "r"(a));
}
__device__ __forceinline__ void ldsm4t(uint32_t* r0, uint32_t* r1, uint32_t a) {
    asm volatile("ldmatrix.sync.aligned.m8n8.x4.trans.shared.b16 {%0,%1,%2,%3},[%4];"
        : "=r"(r0[0]), "=r"(r0[1]), "=r"(r1[0]), "=r"(r1[1]) : "r"(a));
}
__device__ __forceinline__ void ldsm4t4(uint32_t* r, uint32_t a) {
    asm volatile("ldmatrix.sync.aligned.m8n8.x4.trans.shared.b16 {%0,%1,%2,%3},[%4];"
        : "=r"(r[0]), "=r"(r[1]), "=r"(r[2]), "=r"(r[3]) : "r"(a));
}
__device__ __forceinline__ void mma_f16(float* d, const uint32_t* a,
                                        const uint32_t* b) {
    asm volatile("mma.sync.aligned.m16n8k16.row.col.f32.f16.f16.f32 "
        "{%0,%1,%2,%3},{%4,%5,%6,%7},{%8,%9},{%0,%1,%2,%3};"
        : "+f"(d[0]), "+f"(d[1]), "+f"(d[2]), "+f"(d[3])
        : "r"(a[0]), "r"(a[1]), "r"(a[2]), "r"(a[3]), "r"(b[0]), "r"(b[1]));
}
__device__ __forceinline__ uint32_t swz(int r, int c) {
    return (uint32_t)(r * 128 + ((c ^ (r & 7)) << 4));
}

// =================== fp32 -> fp16 ===================
__global__ __launch_bounds__(256) void convh_k(
    const float* __restrict__ in, __half* __restrict__ hi, int n)
{
    int i = (blockIdx.x * 256 + threadIdx.x) * 4;
    if (i >= n) return;
    float4 v = *(const float4*)(in + i);
    *(uint32_t*)(hi + i)     = packh(v.x, v.y);
    *(uint32_t*)(hi + i + 2) = packh(v.z, v.w);
}

// ============ persistent single-pass fp16 GEMM (4 warps, 64x64 tiles) ============
#define SA_PITCH 40
#define SB_PITCH 136
#define AH_OFF 0
#define BH_OFF 5120
#define STG_ELEMS 9472
#define GEMM_SMEM (3 * STG_ELEMS * 2)
#define GEMM_GRID 304

__device__ __forceinline__ void prefetch_tiles(
    __half* smbuf, const __half* A, const __half* B,
    int bm, int bn, int N, int K, int k0, int buf, int tid)
{
    __half* sb = smbuf + buf * STG_ELEMS;
    #pragma unroll
    for (int it = 0; it < 8; it++) {
        int gi = tid + it * 128;
        if (gi < 512) {
            int r = gi >> 2, c = gi & 3;
            cp16(sb + AH_OFF + r * SA_PITCH + c * 8,
                 A + (size_t)(bm + r) * K + k0 + c * 8);
        } else {
            int g = gi - 512;
            int r = g >> 4, c = g & 15;
            cp16(sb + BH_OFF + r * SB_PITCH + c * 8,
                 B + (size_t)(k0 + r) * N + bn + c * 8);
        }
    }
    asm volatile("cp.async.commit_group;" ::: "memory");
}

template <int F16OUT>
__global__ __launch_bounds__(128, 2) void gemm1c_k(
    const __half* __restrict__ A, const __half* __restrict__ B,
    float* __restrict__ C, __half* __restrict__ Ch, int M, int N, int K)
{
    extern __shared__ __half smbuf[];
    int tid = threadIdx.x, lane = tid & 31, warp = tid >> 5;
    int wm = (warp >> 1) * 64, wn = (warp & 1) * 64;
    uint32_t smb = (uint32_t)__cvta_generic_to_shared(smbuf);
    int NK = K >> 5;
    int ntn = N >> 7;
    int tcount = (M >> 7) * ntn;

    for (int tile = blockIdx.x; tile < tcount; tile += gridDim.x) {
        int bm = (tile / ntn) << 7, bn = (tile % ntn) << 7;
        float acc[4][8][4] = {};

        prefetch_tiles(smbuf, A, B, bm, bn, N, K, 0, 0, tid);
        if (NK > 1)
            prefetch_tiles(smbuf, A, B, bm, bn, N, K, 32, 1, tid);

        int scur = 0, snx2 = 2;
        for (int kt = 0; kt < NK; kt++) {
            if (kt + 1 < NK)
                asm volatile("cp.async.wait_group 1;" ::: "memory");
            else
                asm volatile("cp.async.wait_group 0;" ::: "memory");
            __syncthreads();
            if (kt + 2 < NK)
                prefetch_tiles(smbuf, A, B, bm, bn, N, K,
                               (kt + 2) << 5, snx2, tid);
            int sb = scur * STG_ELEMS;
            #pragma unroll
            for (int ks = 0; ks < 2; ks++) {
                uint32_t aH[4][4], bH[8][2];
                int arow = lane & 15;
                int acb = ks * 32 + ((lane >> 4) << 4);
                #pragma unroll
                for (int mt = 0; mt < 4; mt++) {
                    uint32_t ad = smb + (uint32_t)((sb + AH_OFF) * 2
                                + (wm + mt * 16 + arow) * (SA_PITCH * 2) + acb);
                    ldsm4(aH[mt], ad);
                }
                int bk = ks * 16 + (lane & 15);
                int bcb = (wn + ((lane >> 4) << 3)) * 2;
                #pragma unroll
                for (int p = 0; p < 4; p++) {
                    uint32_t bd = smb + (uint32_t)((sb + BH_OFF) * 2
                                + bk * (SB_PITCH * 2) + bcb + p * 32);
                    ldsm4t(bH[2 * p], bH[2 * p + 1], bd);
                }
                #pragma unroll
                for (int mt = 0; mt < 4; mt++)
                    #pragma unroll
                    for (int nt = 0; nt < 8; nt++)
                        mma_f16(acc[mt][nt], aH[mt], bH[nt]);
            }
            scur = (scur == 2) ? 0 : scur + 1;
            snx2 = (snx2 == 2) ? 0 : snx2 + 1;
        }
        #pragma unroll
        for (int mt = 0; mt < 4; mt++) {
            #pragma unroll
            for (int nt = 0; nt < 8; nt++) {
                int r = bm + wm + mt * 16 + (lane >> 2);
                int c = bn + wn + nt * 8 + ((lane & 3) << 1);
                if (F16OUT) {
                    *(uint32_t*)(Ch + (size_t)r * N + c) =
                        packh(acc[mt][nt][0], acc[mt][nt][1]);
                    *(uint32_t*)(Ch + (size_t)(r + 8) * N + c) =
                        packh(acc[mt][nt][2], acc[mt][nt][3]);
                } else {
                    *(float2*)&C[(size_t)r * N + c] =
                        make_float2(acc[mt][nt][0], acc[mt][nt][1]);
                    *(float2*)&C[(size_t)(r + 8) * N + c] =
                        make_float2(acc[mt][nt][2], acc[mt][nt][3]);
                }
            }
        }
        __syncthreads();   // protect smem buffers before next tile's prefetch
    }
}

// =================== RoPE + grouped scatter (fp16 in/out) ===================
__global__ __launch_bounds__(256) void rope_k(
    const float* __restrict__ fcos, const float* __restrict__ fsin)
{
    unsigned id = blockIdx.x * 256u + threadIdx.x;
    int j = id & 31;
    int t = (id >> 5) & (TT - 1);
    int h = (id >> 17) & (HH - 1);
    int b = id >> 21;
    const __half* row = g_qkvh + (size_t)(b * TT + t) * (3 * CC);
    float2 qv = __half22float2(*(const __half2*)(row + h * HSD + 2 * j));
    float2 kv = __half22float2(*(const __half2*)(row + CC + h * HSD + 2 * j));
    float2 vv = __half22float2(*(const __half2*)(row + 2 * CC + h * HSD + 2 * j));
    float c = fcos[t * 32 + j];
    float s = fsin[t * 32 + j];
    float2 qo = make_float2(qv.x * c - qv.y * s, qv.x * s + qv.y * c);
    float2 ko = make_float2(kv.x * c - kv.y * s, kv.x * s + kv.y * c);
    int h2 = t & 15;
    int gq = h >> 1;
    int gtq = ((h & 1) << 8) | (t >> 4);
    size_t qidx = (((size_t)((b * HH + h2) * GG + gq) * GTT + gtq) * HSD) + 2 * j;
    *(uint32_t*)(g_qh + qidx) = packh(qo.x, qo.y);
    *(uint32_t*)(g_kh + qidx) = packh(ko.x, ko.y);
    int gv = t >> 9, gtv = t & 511;
    size_t vidx = (((size_t)((b * HH + h) * GG + gv) * GTT + gtv) * HSD) + 2 * j;
    *(uint32_t*)(g_vh + vidx) = packh(vv.x, vv.y);
}

// =================== tensor-core block-causal flash attention ===================
// 3 K/V buffers (16KB each) + Q (16KB) = 64KB; single barrier per k-tile.
#define ATT_SMEM 65536

__global__ __launch_bounds__(256) void attn_k() {
    extern __shared__ __align__(16) char smraw[];
    uint32_t smb = (uint32_t)__cvta_generic_to_shared(smraw);
    int tid = threadIdx.x, lane = tid & 31, w = tid >> 5;
    int bx = blockIdx.x;
    int qi = 3 - (bx & 3);          // heavy tiles first
    int g  = (bx >> 2) & 7;
    int h  = (bx >> 5) & 15;
    int b  = bx >> 9;
    size_t gb = ((size_t)((b * HH + h) * GG + g)) * GTT * HSD;
    const __half* Qhp = g_qh + gb + (size_t)(128 * qi) * HSD;
    const __half* arrp[2] = { g_kh + gb, g_vh + gb };

    // stage Q (128x64 fp16 = 16KB) at offset 49152
    #pragma unroll
    for (int it = 0; it < 4; it++) {
        int cid = tid + it * 256;
        int r = cid >> 3, c = cid & 7;
        cp16s(smb + 49152 + swz(r, c), Qhp + r * HSD + c * 8);
    }
    asm volatile("cp.async.commit_group;" ::: "memory");
    asm volatile("cp.async.wait_group 0;" ::: "memory");
    __syncthreads();

    uint32_t qhf[4][4];
    int rq = w * 16;
    int sub = lane >> 3;
    #pragma unroll
    for (int kk = 0; kk < 4; kk++) {
        int r = rq + (sub & 1) * 8 + (lane & 7);
        int c = 2 * kk + (sub >> 1);
        ldsm4(qhf[kk], smb + 49152 + swz(r, c));
    }
    __syncthreads();

    int ntiles = 2 * qi + 2;

    // K/V tile loader: buffer buf at smb + buf*16384 (K at +0, V at +8192)
    auto load_kv = [&](int kt, int buf) {
        #pragma unroll
        for (int it = 0; it < 4; it++) {
            int cid = tid + it * 256;
            int arr = cid >> 9;
            int rc = cid & 511;
            int r = rc >> 3, c = rc & 7;
            cp16s(smb + buf * 16384 + arr * 8192 + swz(r, c),
                  arrp[arr] + (size_t)(kt * 64 + r) * HSD + c * 8);
        }
        asm volatile("cp.async.commit_group;" ::: "memory");
    };

    load_kv(0, 0);
    if (ntiles > 1) load_kv(1, 1);

    float oacc[8][4] = {};
    float m_lo = -1e30f, m_hi = -1e30f, l_lo = 0.f, l_hi = 0.f;
    int scur = 0, snx2 = 2;

    for (int kt = 0; kt < ntiles; kt++) {
        if (kt + 1 < ntiles)
            asm volatile("cp.async.wait_group 1;" ::: "memory");
        else
            asm volatile("cp.async.wait_group 0;" ::: "memory");
        __syncthreads();
        if (kt + 2 < ntiles) load_kv(kt + 2, snx2);
        uint32_t kb0 = smb + scur * 16384;

        // ---- S = Q Kh^T ----
        float sacc[8][4] = {};
        #pragma unroll
        for (int kk = 0; kk < 4; kk++) {
            #pragma unroll
            for (int tp = 0; tp < 4; tp++) {
                uint32_t kh4[4];
                int r = tp * 16 + (sub >> 1) * 8 + (lane & 7);
                int c = 2 * kk + (sub & 1);
                ldsm4(kh4, kb0 + swz(r, c));
                mma_f16(sacc[2 * tp],     qhf[kk], kh4);
                mma_f16(sacc[2 * tp + 1], qhf[kk], kh4 + 2);
            }
        }

        int rowl = 128 * qi + w * 16 + (lane >> 2);
        bool nm = (kt * 64 + 63) > (128 * qi + w * 16);
        #pragma unroll
        for (int t = 0; t < 8; t++) {
            #pragma unroll
            for (int e = 0; e < 4; e++) {
                float s = sacc[t][e] * 0.125f;
                if (nm) {
                    int col = kt * 64 + t * 8 + ((lane & 3) << 1) + (e & 1);
                    int row = rowl + ((e & 2) ? 8 : 0);
                    if (col > row) s = -1e30f;
                }
                sacc[t][e] = s;
            }
        }

        float mlo = -1e30f, mhi = -1e30f;
        #pragma unroll
        for (int t = 0; t < 8; t++) {
            mlo = fmaxf(mlo, fmaxf(sacc[t][0], sacc[t][1]));
            mhi = fmaxf(mhi, fmaxf(sacc[t][2], sacc[t][3]));
        }
        mlo = fmaxf(mlo, __shfl_xor_sync(0xffffffffu, mlo, 1));
        mlo = fmaxf(mlo, __shfl_xor_sync(0xffffffffu, mlo, 2));
        mhi = fmaxf(mhi, __shfl_xor_sync(0xffffffffu, mhi, 1));
        mhi = fmaxf(mhi, __shfl_xor_sync(0xffffffffu, mhi, 2));
        float nmlo = fmaxf(m_lo, mlo), nmhi = fmaxf(m_hi, mhi);
        float clo = __expf(m_lo - nmlo), chi = __expf(m_hi - nmhi);
        m_lo = nmlo; m_hi = nmhi;
        float slo = 0.f, shi = 0.f;
        #pragma unroll
        for (int t = 0; t < 8; t++) {
            float p0 = __expf(sacc[t][0] - nmlo);
            float p1 = __expf(sacc[t][1] - nmlo);
            float p2 = __expf(sacc[t][2] - nmhi);
            float p3 = __expf(sacc[t][3] - nmhi);
            sacc[t][0] = p0; sacc[t][1] = p1; sacc[t][2] = p2; sacc[t][3] = p3;
            slo += p0 + p1; shi += p2 + p3;
        }
        slo += __shfl_xor_sync(0xffffffffu, slo, 1);
        slo += __shfl_xor_sync(0xffffffffu, slo, 2);
        shi += __shfl_xor_sync(0xffffffffu, shi, 1);
        shi += __shfl_xor_sync(0xffffffffu, shi, 2);
        l_lo = l_lo * clo + slo;
        l_hi = l_hi * chi + shi;
        #pragma unroll
        for (int t = 0; t < 8; t++) {
            oacc[t][0] *= clo; oacc[t][1] *= clo;
            oacc[t][2] *= chi; oacc[t][3] *= chi;
        }

        // ---- O += P Vh ----
        #pragma unroll
        for (int jk = 0; jk < 4; jk++) {
            uint32_t aph[4];
            {
                int t0 = 2 * jk, t1 = t0 + 1;
                aph[0] = packh(sacc[t0][0], sacc[t0][1]);
                aph[1] = packh(sacc[t0][2], sacc[t0][3]);
                aph[2] = packh(sacc[t1][0], sacc[t1][1]);
                aph[3] = packh(sacc[t1][2], sacc[t1][3]);
            }
            #pragma unroll
            for (int dp = 0; dp < 4; dp++) {
                uint32_t vh4[4];
                int r = jk * 16 + (sub & 1) * 8 + (lane & 7);
                int c = 2 * dp + (sub >> 1);
                ldsm4t4(vh4, kb0 + 8192 + swz(r, c));
                mma_f16(oacc[2 * dp],     aph, vh4);
                mma_f16(oacc[2 * dp + 1], aph, vh4 + 2);
            }
        }
        scur = (scur == 2) ? 0 : scur + 1;
        snx2 = (snx2 == 2) ? 0 : snx2 + 1;
    }

    float ilo = 1.0f / l_lo, ihi = 1.0f / l_hi;
    size_t tau = (size_t)b * TT + g * GTT + 128 * qi + w * 16 + (lane >> 2);
    int colb = h * HSD + ((lane & 3) << 1);
    #pragma unroll
    for (int t = 0; t < 8; t++) {
        float v0 = oacc[t][0] * ilo, v1 = oacc[t][1] * ilo;
        float v2 = oacc[t][2] * ihi, v3 = oacc[t][3] * ihi;
        size_t o0 = tau * CC + colb + t * 8;
        size_t o1 = (tau + 8) * CC + colb + t * 8;
        *(uint32_t*)(g_obh + o0) = packh(v0, v1);
        *(uint32_t*)(g_obh + o1) = packh(v2, v3);
    }
}

// =================== Pooling (qb/kb/vb; L=1 attention is identity) ===================
__global__ __launch_bounds__(64) void pool_k(
    const float* __restrict__ qp, const float* __restrict__ kp,
    const float* __restrict__ vp, float* __restrict__ out)
{
    int bx = blockIdx.x;
    int which = bx / 448;
    int rem = bx - which * 448;
    int g = rem % 7;
    int bh = rem / 7;
    size_t base = ((size_t)bh * GG + g) * GTT * HSD;
    const __half* sh = (which == 0 ? g_qh : (which == 1 ? g_kh : g_vh)) + base;
    const float* proj = (which == 0 ? qp : (which == 1 ? kp : vp));
    int hs = threadIdx.x;
    float acc = 0.f;
    #pragma unroll 8
    for (int t = 0; t < GTT; t++)
        acc = fmaf(__half2float(sh[(size_t)t * HSD + hs]), proj[t], acc);
    out[(size_t)BB * TT * CC + (size_t)which * (BB * HH * 7 * HSD)
        + (size_t)(bh * 7 + g) * HSD + hs] = acc;
}

// =================== launch ===================
extern "C" void kernel_launch(void* const* d_in, const int* in_sizes, int n_in,
                              void* d_out, int out_size) {
    (void)in_sizes; (void)n_in; (void)out_size;
    const float* x    = (const float*)d_in[0];
    const float* Wqkv = (const float*)d_in[1];
    const float* Wo   = (const float*)d_in[2];
    const float* qp   = (const float*)d_in[3];
    const float* kp   = (const float*)d_in[4];
    const float* vp   = (const float*)d_in[5];
    const float* fc   = (const float*)d_in[6];
    const float* fs   = (const float*)d_in[7];
    float* out = (float*)d_out;

    __half *qkvh, *xh, *wqh, *woh, *obh;
    cudaGetSymbolAddress((void**)&qkvh, g_qkvh);
    cudaGetSymbolAddress((void**)&xh, g_xh);
    cudaGetSymbolAddress((void**)&wqh, g_wqh);
    cudaGetSymbolAddress((void**)&woh, g_woh);
    cudaGetSymbolAddress((void**)&obh, g_obh);

    cudaFuncSetAttribute(attn_k, cudaFuncAttributeMaxDynamicSharedMemorySize,
                         ATT_SMEM);
    cudaFuncSetAttribute(gemm1c_k<0>, cudaFuncAttributeMaxDynamicSharedMemorySize,
                         GEMM_SMEM);
    cudaFuncSetAttribute(gemm1c_k<1>, cudaFuncAttributeMaxDynamicSharedMemorySize,
                         GEMM_SMEM);

    // 0) convert operands to fp16
    int nx = BB * TT * CC;
    convh_k<<<(nx / 4 + 255) / 256, 256>>>(x, xh, nx);
    int nwq = CC * 3 * CC;
    convh_k<<<(nwq / 4 + 255) / 256, 256>>>(Wqkv, wqh, nwq);
    int nwo = CC * CC;
    convh_k<<<(nwo / 4 + 255) / 256, 256>>>(Wo, woh, nwo);

    // 1) qkv = x @ Wqkv  (persistent single-pass fp16, fp16 output)
    gemm1c_k<1><<<GEMM_GRID, 128, GEMM_SMEM>>>(xh, wqh, nullptr, qkvh,
                                               BB * TT, 3 * CC, CC);
    // 2) rope + grouped scatter (fp16)
    rope_k<<<(BB * HH * TT * 32) / 256, 256>>>(fc, fs);
    // 3) tensor-core block-causal attention (3-stage, single barrier per tile)
    attn_k<<<BB * HH * GG * 4, 256, ATT_SMEM>>>();
    // 4) qb/kb/vb pools (tail of d_out)
    pool_k<<<3 * BB * HH * 7, 64>>>(qp, kp, vp, out);
    // 5) out = o @ Wo (persistent, fp32 output)
    gemm1c_k<0><<<GEMM_GRID, 128, GEMM_SMEM>>>(obh, woh, out, nullptr,
                                               BB * TT, CC, CC);
}

// round 16
// speedup vs baseline: 1.1276x; 1.1276x over previous
#include <cuda_runtime.h>
#include <cuda_fp16.h>
#include <cstdint>
#include <cstddef>

#define BB 4
#define TT 4096
#define CC 1024
#define HH 16
#define GG 8
#define HSD 64
#define GTT 512

// ---- scratch (static device globals; no runtime allocation allowed) ----
__device__ __align__(16) __half g_qkvh[(size_t)BB*TT*3*CC];   // fp16 qkv (96MB)
__device__ __align__(16) __half g_qh[(size_t)BB*HH*GG*GTT*HSD];
__device__ __align__(16) __half g_kh[(size_t)BB*HH*GG*GTT*HSD];
__device__ __align__(16) __half g_vh[(size_t)BB*HH*GG*GTT*HSD];
__device__ __align__(16) __half g_xh[(size_t)BB*TT*CC];
__device__ __align__(16) __half g_wqh[(size_t)CC*3*CC];
__device__ __align__(16) __half g_woh[(size_t)CC*CC];
__device__ __align__(16) __half g_obh[(size_t)BB*TT*CC];

// =================== small helpers ===================
__device__ __forceinline__ uint32_t packh(float lo, float hi) {
    uint32_t r;
    asm("cvt.rn.f16x2.f32 %0,%1,%2;" : "=r"(r) : "f"(hi), "f"(lo));
    return r;
}
__device__ __forceinline__ void cp16(void* s, const void* g) {
    uint32_t sa = (uint32_t)__cvta_generic_to_shared(s);
    asm volatile("cp.async.cg.shared.global [%0], [%1], 16;" :: "r"(sa), "l"(g));
}
__device__ __forceinline__ void cp16s(uint32_t sa, const void* g) {
    asm volatile("cp.async.cg.shared.global [%0], [%1], 16;" :: "r"(sa), "l"(g));
}
__device__ __forceinline__ void ldsm4(uint32_t* r, uint32_t a) {
    asm volatile("ldmatrix.sync.aligned.m8n8.x4.shared.b16 {%0,%1,%2,%3},[%4];"
        : "=r"(r[0]), "=r"(r[1]), "=r"(r[2]), "=r"(r[3]) : "r"(a));
}
__device__ __forceinline__ void ldsm4t(uint32_t* r0, uint32_t* r1, uint32_t a) {
    asm volatile("ldmatrix.sync.aligned.m8n8.x4.trans.shared.b16 {%0,%1,%2,%3},[%4];"
        : "=r"(r0[0]), "=r"(r0[1]), "=r"(r1[0]), "=r"(r1[1]) : "r"(a));
}
__device__ __forceinline__ void ldsm4t4(uint32_t* r, uint32_t a) {
    asm volatile("ldmatrix.sync.aligned.m8n8.x4.trans.shared.b16 {%0,%1,%2,%3},[%4];"
        : "=r"(r[0]), "=r"(r[1]), "=r"(r[2]), "=r"(r[3]) : "r"(a));
}
__device__ __forceinline__ void mma_f16(float* d, const uint32_t* a,
                                        const uint32_t* b) {
    asm volatile("mma.sync.aligned.m16n8k16.row.col.f32.f16.f16.f32 "
        "{%0,%1,%2,%3},{%4,%5,%6,%7},{%8,%9},{%0,%1,%2,%3};"
        : "+f"(d[0]), "+f"(d[1]), "+f"(d[2]), "+f"(d[3])
        : "r"(a[0]), "r"(a[1]), "r"(a[2]), "r"(a[3]), "r"(b[0]), "r"(b[1]));
}
__device__ __forceinline__ uint32_t swz(int r, int c) {
    return (uint32_t)(r * 128 + ((c ^ (r & 7)) << 4));
}

// =================== fp32 -> fp16 ===================
__global__ __launch_bounds__(256) void convh_k(
    const float* __restrict__ in, __half* __restrict__ hi, int n)
{
    int i = (blockIdx.x * 256 + threadIdx.x) * 4;
    if (i >= n) return;
    float4 v = *(const float4*)(in + i);
    *(uint32_t*)(hi + i)     = packh(v.x, v.y);
    *(uint32_t*)(hi + i + 2) = packh(v.z, v.w);
}

// =================== single-pass fp16 GEMM (4 warps, 64x64 tiles) ===================
// Block 128x128, warp tile 64x64, 2 CTAs/SM, 3-stage cp.async. (R14 proven config)
#define SA_PITCH 40
#define SB_PITCH 136
#define AH_OFF 0
#define BH_OFF 5120
#define STG_ELEMS 9472
#define GEMM_SMEM (3 * STG_ELEMS * 2)

__device__ __forceinline__ void prefetch_tiles(
    __half* smbuf, const __half* A, const __half* B,
    int bm, int bn, int N, int K, int k0, int buf, int tid)
{
    __half* sb = smbuf + buf * STG_ELEMS;
    #pragma unroll
    for (int it = 0; it < 8; it++) {
        int gi = tid + it * 128;
        if (gi < 512) {                          // A: 128 rows x 4 granules
            int r = gi >> 2, c = gi & 3;
            cp16(sb + AH_OFF + r * SA_PITCH + c * 8,
                 A + (size_t)(bm + r) * K + k0 + c * 8);
        } else {                                 // B: 32 rows x 16 granules
            int g = gi - 512;
            int r = g >> 4, c = g & 15;
            cp16(sb + BH_OFF + r * SB_PITCH + c * 8,
                 B + (size_t)(k0 + r) * N + bn + c * 8);
        }
    }
    asm volatile("cp.async.commit_group;" ::: "memory");
}

template <int F16OUT>
__global__ __launch_bounds__(128, 2) void gemm1c_k(
    const __half* __restrict__ A, const __half* __restrict__ B,
    float* __restrict__ C, __half* __restrict__ Ch, int M, int N, int K)
{
    extern __shared__ __half smbuf[];
    int tid = threadIdx.x, lane = tid & 31, warp = tid >> 5;
    int bm = blockIdx.y * 128, bn = blockIdx.x * 128;
    int wm = (warp >> 1) * 64, wn = (warp & 1) * 64;
    uint32_t smb = (uint32_t)__cvta_generic_to_shared(smbuf);
    float acc[4][8][4] = {};
    int NK = K >> 5;

    prefetch_tiles(smbuf, A, B, bm, bn, N, K, 0, 0, tid);
    if (NK > 1)
        prefetch_tiles(smbuf, A, B, bm, bn, N, K, 32, 1, tid);

    int scur = 0, snx2 = 2;
    for (int kt = 0; kt < NK; kt++) {
        if (kt + 1 < NK)
            asm volatile("cp.async.wait_group 1;" ::: "memory");
        else
            asm volatile("cp.async.wait_group 0;" ::: "memory");
        __syncthreads();
        if (kt + 2 < NK)
            prefetch_tiles(smbuf, A, B, bm, bn, N, K,
                           (kt + 2) << 5, snx2, tid);
        int sb = scur * STG_ELEMS;
        #pragma unroll
        for (int ks = 0; ks < 2; ks++) {
            uint32_t aH[4][4], bH[8][2];
            int arow = lane & 15;
            int acb = ks * 32 + ((lane >> 4) << 4);
            #pragma unroll
            for (int mt = 0; mt < 4; mt++) {
                uint32_t ad = smb + (uint32_t)((sb + AH_OFF) * 2
                            + (wm + mt * 16 + arow) * (SA_PITCH * 2) + acb);
                ldsm4(aH[mt], ad);
            }
            int bk = ks * 16 + (lane & 15);
            int bcb = (wn + ((lane >> 4) << 3)) * 2;
            #pragma unroll
            for (int p = 0; p < 4; p++) {
                uint32_t bd = smb + (uint32_t)((sb + BH_OFF) * 2
                            + bk * (SB_PITCH * 2) + bcb + p * 32);
                ldsm4t(bH[2 * p], bH[2 * p + 1], bd);
            }
            #pragma unroll
            for (int mt = 0; mt < 4; mt++)
                #pragma unroll
                for (int nt = 0; nt < 8; nt++)
                    mma_f16(acc[mt][nt], aH[mt], bH[nt]);
        }
        scur = (scur == 2) ? 0 : scur + 1;
        snx2 = (snx2 == 2) ? 0 : snx2 + 1;
    }
    #pragma unroll
    for (int mt = 0; mt < 4; mt++) {
        #pragma unroll
        for (int nt = 0; nt < 8; nt++) {
            int r = bm + wm + mt * 16 + (lane >> 2);
            int c = bn + wn + nt * 8 + ((lane & 3) << 1);
            if (F16OUT) {
                *(uint32_t*)(Ch + (size_t)r * N + c) =
                    packh(acc[mt][nt][0], acc[mt][nt][1]);
                *(uint32_t*)(Ch + (size_t)(r + 8) * N + c) =
                    packh(acc[mt][nt][2], acc[mt][nt][3]);
            } else {
                *(float2*)&C[(size_t)r * N + c] =
                    make_float2(acc[mt][nt][0], acc[mt][nt][1]);
                *(float2*)&C[(size_t)(r + 8) * N + c] =
                    make_float2(acc[mt][nt][2], acc[mt][nt][3]);
            }
        }
    }
}

// =================== RoPE + grouped scatter (fp16 in/out) ===================
__global__ __launch_bounds__(256) void rope_k(
    const float* __restrict__ fcos, const float* __restrict__ fsin)
{
    unsigned id = blockIdx.x * 256u + threadIdx.x;
    int j = id & 31;
    int t = (id >> 5) & (TT - 1);
    int h = (id >> 17) & (HH - 1);
    int b = id >> 21;
    const __half* row = g_qkvh + (size_t)(b * TT + t) * (3 * CC);
    float2 qv = __half22float2(*(const __half2*)(row + h * HSD + 2 * j));
    float2 kv = __half22float2(*(const __half2*)(row + CC + h * HSD + 2 * j));
    float2 vv = __half22float2(*(const __half2*)(row + 2 * CC + h * HSD + 2 * j));
    float c = fcos[t * 32 + j];
    float s = fsin[t * 32 + j];
    float2 qo = make_float2(qv.x * c - qv.y * s, qv.x * s + qv.y * c);
    float2 ko = make_float2(kv.x * c - kv.y * s, kv.x * s + kv.y * c);
    int h2 = t & 15;
    int gq = h >> 1;
    int gtq = ((h & 1) << 8) | (t >> 4);
    size_t qidx = (((size_t)((b * HH + h2) * GG + gq) * GTT + gtq) * HSD) + 2 * j;
    *(uint32_t*)(g_qh + qidx) = packh(qo.x, qo.y);
    *(uint32_t*)(g_kh + qidx) = packh(ko.x, ko.y);
    int gv = t >> 9, gtv = t & 511;
    size_t vidx = (((size_t)((b * HH + h) * GG + gv) * GTT + gtv) * HSD) + 2 * j;
    *(uint32_t*)(g_vh + vidx) = packh(vv.x, vv.y);
}

// =================== tensor-core block-causal flash attention ===================
// 3 K/V buffers (16KB each) + Q (16KB) = 64KB; single barrier per k-tile.
#define ATT_SMEM 65536

__global__ __launch_bounds__(256) void attn_k() {
    extern __shared__ __align__(16) char smraw[];
    uint32_t smb = (uint32_t)__cvta_generic_to_shared(smraw);
    int tid = threadIdx.x, lane = tid & 31, w = tid >> 5;
    int bx = blockIdx.x;
    int qi = 3 - (bx & 3);          // heavy tiles first
    int g  = (bx >> 2) & 7;
    int h  = (bx >> 5) & 15;
    int b  = bx >> 9;
    size_t gb = ((size_t)((b * HH + h) * GG + g)) * GTT * HSD;
    const __half* Qhp = g_qh + gb + (size_t)(128 * qi) * HSD;
    const __half* arrp[2] = { g_kh + gb, g_vh + gb };

    // stage Q (128x64 fp16 = 16KB) at offset 49152
    #pragma unroll
    for (int it = 0; it < 4; it++) {
        int cid = tid + it * 256;
        int r = cid >> 3, c = cid & 7;
        cp16s(smb + 49152 + swz(r, c), Qhp + r * HSD + c * 8);
    }
    asm volatile("cp.async.commit_group;" ::: "memory");
    asm volatile("cp.async.wait_group 0;" ::: "memory");
    __syncthreads();

    uint32_t qhf[4][4];
    int rq = w * 16;
    int sub = lane >> 3;
    #pragma unroll
    for (int kk = 0; kk < 4; kk++) {
        int r = rq + (sub & 1) * 8 + (lane & 7);
        int c = 2 * kk + (sub >> 1);
        ldsm4(qhf[kk], smb + 49152 + swz(r, c));
    }
    __syncthreads();

    int ntiles = 2 * qi + 2;

    auto load_kv = [&](int kt, int buf) {
        #pragma unroll
        for (int it = 0; it < 4; it++) {
            int cid = tid + it * 256;
            int arr = cid >> 9;
            int rc = cid & 511;
            int r = rc >> 3, c = rc & 7;
            cp16s(smb + buf * 16384 + arr * 8192 + swz(r, c),
                  arrp[arr] + (size_t)(kt * 64 + r) * HSD + c * 8);
        }
        asm volatile("cp.async.commit_group;" ::: "memory");
    };

    load_kv(0, 0);
    if (ntiles > 1) load_kv(1, 1);

    float oacc[8][4] = {};
    float m_lo = -1e30f, m_hi = -1e30f, l_lo = 0.f, l_hi = 0.f;
    int scur = 0, snx2 = 2;

    for (int kt = 0; kt < ntiles; kt++) {
        if (kt + 1 < ntiles)
            asm volatile("cp.async.wait_group 1;" ::: "memory");
        else
            asm volatile("cp.async.wait_group 0;" ::: "memory");
        __syncthreads();
        if (kt + 2 < ntiles) load_kv(kt + 2, snx2);
        uint32_t kb0 = smb + scur * 16384;

        float sacc[8][4] = {};
        #pragma unroll
        for (int kk = 0; kk < 4; kk++) {
            #pragma unroll
            for (int tp = 0; tp < 4; tp++) {
                uint32_t kh4[4];
                int r = tp * 16 + (sub >> 1) * 8 + (lane & 7);
                int c = 2 * kk + (sub & 1);
                ldsm4(kh4, kb0 + swz(r, c));
                mma_f16(sacc[2 * tp],     qhf[kk], kh4);
                mma_f16(sacc[2 * tp + 1], qhf[kk], kh4 + 2);
            }
        }

        int rowl = 128 * qi + w * 16 + (lane >> 2);
        bool nm = (kt * 64 + 63) > (128 * qi + w * 16);
        #pragma unroll
        for (int t = 0; t < 8; t++) {
            #pragma unroll
            for (int e = 0; e < 4; e++) {
                float s = sacc[t][e] * 0.125f;
                if (nm) {
                    int col = kt * 64 + t * 8 + ((lane & 3) << 1) + (e & 1);
                    int row = rowl + ((e & 2) ? 8 : 0);
                    if (col > row) s = -1e30f;
                }
                sacc[t][e] = s;
            }
        }

        float mlo = -1e30f, mhi = -1e30f;
        #pragma unroll
        for (int t = 0; t < 8; t++) {
            mlo = fmaxf(mlo, fmaxf(sacc[t][0], sacc[t][1]));
            mhi = fmaxf(mhi, fmaxf(sacc[t][2], sacc[t][3]));
        }
        mlo = fmaxf(mlo, __shfl_xor_sync(0xffffffffu, mlo, 1));
        mlo = fmaxf(mlo, __shfl_xor_sync(0xffffffffu, mlo, 2));
        mhi = fmaxf(mhi, __shfl_xor_sync(0xffffffffu, mhi, 1));
        mhi = fmaxf(mhi, __shfl_xor_sync(0xffffffffu, mhi, 2));
        float nmlo = fmaxf(m_lo, mlo), nmhi = fmaxf(m_hi, mhi);
        float clo = __expf(m_lo - nmlo), chi = __expf(m_hi - nmhi);
        m_lo = nmlo; m_hi = nmhi;
        float slo = 0.f, shi = 0.f;
        #pragma unroll
        for (int t = 0; t < 8; t++) {
            float p0 = __expf(sacc[t][0] - nmlo);
            float p1 = __expf(sacc[t][1] - nmlo);
            float p2 = __expf(sacc[t][2] - nmhi);
            float p3 = __expf(sacc[t][3] - nmhi);
            sacc[t][0] = p0; sacc[t][1] = p1; sacc[t][2] = p2; sacc[t][3] = p3;
            slo += p0 + p1; shi += p2 + p3;
        }
        slo += __shfl_xor_sync(0xffffffffu, slo, 1);
        slo += __shfl_xor_sync(0xffffffffu, slo, 2);
        shi += __shfl_xor_sync(0xffffffffu, shi, 1);
        shi += __shfl_xor_sync(0xffffffffu, shi, 2);
        l_lo = l_lo * clo + slo;
        l_hi = l_hi * chi + shi;
        #pragma unroll
        for (int t = 0; t < 8; t++) {
            oacc[t][0] *= clo; oacc[t][1] *= clo;
            oacc[t][2] *= chi; oacc[t][3] *= chi;
        }

        #pragma unroll
        for (int jk = 0; jk < 4; jk++) {
            uint32_t aph[4];
            {
                int t0 = 2 * jk, t1 = t0 + 1;
                aph[0] = packh(sacc[t0][0], sacc[t0][1]);
                aph[1] = packh(sacc[t0][2], sacc[t0][3]);
                aph[2] = packh(sacc[t1][0], sacc[t1][1]);
                aph[3] = packh(sacc[t1][2], sacc[t1][3]);
            }
            #pragma unroll
            for (int dp = 0; dp < 4; dp++) {
                uint32_t vh4[4];
                int r = jk * 16 + (sub & 1) * 8 + (lane & 7);
                int c = 2 * dp + (sub >> 1);
                ldsm4t4(vh4, kb0 + 8192 + swz(r, c));
                mma_f16(oacc[2 * dp],     aph, vh4);
                mma_f16(oacc[2 * dp + 1], aph, vh4 + 2);
            }
        }
        scur = (scur == 2) ? 0 : scur + 1;
        snx2 = (snx2 == 2) ? 0 : snx2 + 1;
    }

    float ilo = 1.0f / l_lo, ihi = 1.0f / l_hi;
    size_t tau = (size_t)b * TT + g * GTT + 128 * qi + w * 16 + (lane >> 2);
    int colb = h * HSD + ((lane & 3) << 1);
    #pragma unroll
    for (int t = 0; t < 8; t++) {
        float v0 = oacc[t][0] * ilo, v1 = oacc[t][1] * ilo;
        float v2 = oacc[t][2] * ihi, v3 = oacc[t][3] * ihi;
        size_t o0 = tau * CC + colb + t * 8;
        size_t o1 = (tau + 8) * CC + colb + t * 8;
        *(uint32_t*)(g_obh + o0) = packh(v0, v1);
        *(uint32_t*)(g_obh + o1) = packh(v2, v3);
    }
}

// =================== Pooling (qb/kb/vb; L=1 attention is identity) ===================
__global__ __launch_bounds__(64) void pool_k(
    const float* __restrict__ qp, const float* __restrict__ kp,
    const float* __restrict__ vp, float* __restrict__ out)
{
    int bx = blockIdx.x;
    int which = bx / 448;
    int rem = bx - which * 448;
    int g = rem % 7;
    int bh = rem / 7;
    size_t base = ((size_t)bh * GG + g) * GTT * HSD;
    const __half* sh = (which == 0 ? g_qh : (which == 1 ? g_kh : g_vh)) + base;
    const float* proj = (which == 0 ? qp : (which == 1 ? kp : vp));
    int hs = threadIdx.x;
    float acc = 0.f;
    #pragma unroll 8
    for (int t = 0; t < GTT; t++)
        acc = fmaf(__half2float(sh[(size_t)t * HSD + hs]), proj[t], acc);
    out[(size_t)BB * TT * CC + (size_t)which * (BB * HH * 7 * HSD)
        + (size_t)(bh * 7 + g) * HSD + hs] = acc;
}

// =================== launch ===================
extern "C" void kernel_launch(void* const* d_in, const int* in_sizes, int n_in,
                              void* d_out, int out_size) {
    (void)in_sizes; (void)n_in; (void)out_size;
    const float* x    = (const float*)d_in[0];
    const float* Wqkv = (const float*)d_in[1];
    const float* Wo   = (const float*)d_in[2];
    const float* qp   = (const float*)d_in[3];
    const float* kp   = (const float*)d_in[4];
    const float* vp   = (const float*)d_in[5];
    const float* fc   = (const float*)d_in[6];
    const float* fs   = (const float*)d_in[7];
    float* out = (float*)d_out;

    __half *qkvh, *xh, *wqh, *woh, *obh;
    cudaGetSymbolAddress((void**)&qkvh, g_qkvh);
    cudaGetSymbolAddress((void**)&xh, g_xh);
    cudaGetSymbolAddress((void**)&wqh, g_wqh);
    cudaGetSymbolAddress((void**)&woh, g_woh);
    cudaGetSymbolAddress((void**)&obh, g_obh);

    cudaFuncSetAttribute(attn_k, cudaFuncAttributeMaxDynamicSharedMemorySize,
                         ATT_SMEM);
    cudaFuncSetAttribute(gemm1c_k<0>, cudaFuncAttributeMaxDynamicSharedMemorySize,
                         GEMM_SMEM);
    cudaFuncSetAttribute(gemm1c_k<1>, cudaFuncAttributeMaxDynamicSharedMemorySize,
                         GEMM_SMEM);

    // 0) convert operands to fp16
    int nx = BB * TT * CC;
    convh_k<<<(nx / 4 + 255) / 256, 256>>>(x, xh, nx);
    int nwq = CC * 3 * CC;
    convh_k<<<(nwq / 4 + 255) / 256, 256>>>(Wqkv, wqh, nwq);
    int nwo = CC * CC;
    convh_k<<<(nwo / 4 + 255) / 256, 256>>>(Wo, woh, nwo);

    // 1) qkv = x @ Wqkv  (single-pass fp16, fp16 output)
    dim3 g1(3 * CC / 128, BB * TT / 128);
    gemm1c_k<1><<<g1, 128, GEMM_SMEM>>>(xh, wqh, nullptr, qkvh,
                                        BB * TT, 3 * CC, CC);
    // 2) rope + grouped scatter (fp16)
    rope_k<<<(BB * HH * TT * 32) / 256, 256>>>(fc, fs);
    // 3) tensor-core block-causal attention (3 buffers, one barrier/tile)
    attn_k<<<BB * HH * GG * 4, 256, ATT_SMEM>>>();
    // 4) qb/kb/vb pools (tail of d_out)
    pool_k<<<3 * BB * HH * 7, 64>>>(qp, kp, vp, out);
    // 5) out = o @ Wo (fp32 output)
    dim3 g2(CC / 128, BB * TT / 128);
    gemm1c_k<0><<<g2, 128, GEMM_SMEM>>>(obh, woh, out, nullptr,
                                        BB * TT, CC, CC);
}

// round 17
// speedup vs baseline: 1.1340x; 1.0056x over previous
#include <cuda_runtime.h>
#include <cuda_fp16.h>
#include <cstdint>
#include <cstddef>

#define BB 4
#define TT 4096
#define CC 1024
#define HH 16
#define GG 8
#define HSD 64
#define GTT 512

// ---- scratch (static device globals; no runtime allocation allowed) ----
__device__ __align__(16) __half g_qkvh[(size_t)BB*TT*3*CC];   // fp16 qkv (96MB)
__device__ __align__(16) __half g_qh[(size_t)BB*HH*GG*GTT*HSD];
__device__ __align__(16) __half g_kh[(size_t)BB*HH*GG*GTT*HSD];
__device__ __align__(16) __half g_vh[(size_t)BB*HH*GG*GTT*HSD];
__device__ __align__(16) __half g_xh[(size_t)BB*TT*CC];
__device__ __align__(16) __half g_wqh[(size_t)CC*3*CC];
__device__ __align__(16) __half g_woh[(size_t)CC*CC];
__device__ __align__(16) __half g_obh[(size_t)BB*TT*CC];

// =================== small helpers ===================
__device__ __forceinline__ uint32_t packh(float lo, float hi) {
    uint32_t r;
    asm("cvt.rn.f16x2.f32 %0,%1,%2;" : "=r"(r) : "f"(hi), "f"(lo));
    return r;
}
__device__ __forceinline__ void cp16(void* s, const void* g) {
    uint32_t sa = (uint32_t)__cvta_generic_to_shared(s);
    asm volatile("cp.async.cg.shared.global [%0], [%1], 16;" :: "r"(sa), "l"(g));
}
__device__ __forceinline__ void cp16s(uint32_t sa, const void* g) {
    asm volatile("cp.async.cg.shared.global [%0], [%1], 16;" :: "r"(sa), "l"(g));
}
__device__ __forceinline__ void ldsm4(uint32_t* r, uint32_t a) {
    asm volatile("ldmatrix.sync.aligned.m8n8.x4.shared.b16 {%0,%1,%2,%3},[%4];"
        : "=r"(r[0]), "=r"(r[1]), "=r"(r[2]), "=r"(r[3]) : "r"(a));
}
__device__ __forceinline__ void ldsm4t(uint32_t* r0, uint32_t* r1, uint32_t a) {
    asm volatile("ldmatrix.sync.aligned.m8n8.x4.trans.shared.b16 {%0,%1,%2,%3},[%4];"
        : "=r"(r0[0]), "=r"(r0[1]), "=r"(r1[0]), "=r"(r1[1]) : "r"(a));
}
__device__ __forceinline__ void ldsm4t4(uint32_t* r, uint32_t a) {
    asm volatile("ldmatrix.sync.aligned.m8n8.x4.trans.shared.b16 {%0,%1,%2,%3},[%4];"
        : "=r"(r[0]), "=r"(r[1]), "=r"(r[2]), "=r"(r[3]) : "r"(a));
}
__device__ __forceinline__ void mma_f16(float* d, const uint32_t* a,
                                        const uint32_t* b) {
    asm volatile("mma.sync.aligned.m16n8k16.row.col.f32.f16.f16.f32 "
        "{%0,%1,%2,%3},{%4,%5,%6,%7},{%8,%9},{%0,%1,%2,%3};"
        : "+f"(d[0]), "+f"(d[1]), "+f"(d[2]), "+f"(d[3])
        : "r"(a[0]), "r"(a[1]), "r"(a[2]), "r"(a[3]), "r"(b[0]), "r"(b[1]));
}
__device__ __forceinline__ uint32_t swz(int r, int c) {
    return (uint32_t)(r * 128 + ((c ^ (r & 7)) << 4));
}

// =================== fp32 -> fp16 ===================
__global__ __launch_bounds__(256) void convh_k(
    const float* __restrict__ in, __half* __restrict__ hi, int n)
{
    int i = (blockIdx.x * 256 + threadIdx.x) * 4;
    if (i >= n) return;
    float4 v = *(const float4*)(in + i);
    *(uint32_t*)(hi + i)     = packh(v.x, v.y);
    *(uint32_t*)(hi + i + 2) = packh(v.z, v.w);
}

// =================== single-pass fp16 GEMM (4 warps, 64x64 tiles) ===================
#define SA_PITCH 40
#define SB_PITCH 136
#define AH_OFF 0
#define BH_OFF 5120
#define STG_ELEMS 9472
#define GEMM_SMEM (3 * STG_ELEMS * 2)

__device__ __forceinline__ void prefetch_tiles(
    __half* smbuf, const __half* A, const __half* B,
    int bm, int bn, int N, int K, int k0, int buf, int tid)
{
    __half* sb = smbuf + buf * STG_ELEMS;
    #pragma unroll
    for (int it = 0; it < 8; it++) {
        int gi = tid + it * 128;
        if (gi < 512) {
            int r = gi >> 2, c = gi & 3;
            cp16(sb + AH_OFF + r * SA_PITCH + c * 8,
                 A + (size_t)(bm + r) * K + k0 + c * 8);
        } else {
            int g = gi - 512;
            int r = g >> 4, c = g & 15;
            cp16(sb + BH_OFF + r * SB_PITCH + c * 8,
                 B + (size_t)(k0 + r) * N + bn + c * 8);
        }
    }
    asm volatile("cp.async.commit_group;" ::: "memory");
}

template <int F16OUT>
__global__ __launch_bounds__(128, 2) void gemm1c_k(
    const __half* __restrict__ A, const __half* __restrict__ B,
    float* __restrict__ C, __half* __restrict__ Ch, int M, int N, int K)
{
    extern __shared__ __half smbuf[];
    int tid = threadIdx.x, lane = tid & 31, warp = tid >> 5;
    int bm = blockIdx.y * 128, bn = blockIdx.x * 128;
    int wm = (warp >> 1) * 64, wn = (warp & 1) * 64;
    uint32_t smb = (uint32_t)__cvta_generic_to_shared(smbuf);
    float acc[4][8][4] = {};
    int NK = K >> 5;

    prefetch_tiles(smbuf, A, B, bm, bn, N, K, 0, 0, tid);
    if (NK > 1)
        prefetch_tiles(smbuf, A, B, bm, bn, N, K, 32, 1, tid);

    int scur = 0, snx2 = 2;
    for (int kt = 0; kt < NK; kt++) {
        if (kt + 1 < NK)
            asm volatile("cp.async.wait_group 1;" ::: "memory");
        else
            asm volatile("cp.async.wait_group 0;" ::: "memory");
        __syncthreads();
        if (kt + 2 < NK)
            prefetch_tiles(smbuf, A, B, bm, bn, N, K,
                           (kt + 2) << 5, snx2, tid);
        int sb = scur * STG_ELEMS;
        #pragma unroll
        for (int ks = 0; ks < 2; ks++) {
            uint32_t aH[4][4], bH[8][2];
            int arow = lane & 15;
            int acb = ks * 32 + ((lane >> 4) << 4);
            #pragma unroll
            for (int mt = 0; mt < 4; mt++) {
                uint32_t ad = smb + (uint32_t)((sb + AH_OFF) * 2
                            + (wm + mt * 16 + arow) * (SA_PITCH * 2) + acb);
                ldsm4(aH[mt], ad);
            }
            int bk = ks * 16 + (lane & 15);
            int bcb = (wn + ((lane >> 4) << 3)) * 2;
            #pragma unroll
            for (int p = 0; p < 4; p++) {
                uint32_t bd = smb + (uint32_t)((sb + BH_OFF) * 2
                            + bk * (SB_PITCH * 2) + bcb + p * 32);
                ldsm4t(bH[2 * p], bH[2 * p + 1], bd);
            }
            #pragma unroll
            for (int mt = 0; mt < 4; mt++)
                #pragma unroll
                for (int nt = 0; nt < 8; nt++)
                    mma_f16(acc[mt][nt], aH[mt], bH[nt]);
        }
        scur = (scur == 2) ? 0 : scur + 1;
        snx2 = (snx2 == 2) ? 0 : snx2 + 1;
    }
    #pragma unroll
    for (int mt = 0; mt < 4; mt++) {
        #pragma unroll
        for (int nt = 0; nt < 8; nt++) {
            int r = bm + wm + mt * 16 + (lane >> 2);
            int c = bn + wn + nt * 8 + ((lane & 3) << 1);
            if (F16OUT) {
                *(uint32_t*)(Ch + (size_t)r * N + c) =
                    packh(acc[mt][nt][0], acc[mt][nt][1]);
                *(uint32_t*)(Ch + (size_t)(r + 8) * N + c) =
                    packh(acc[mt][nt][2], acc[mt][nt][3]);
            } else {
                *(float2*)&C[(size_t)r * N + c] =
                    make_float2(acc[mt][nt][0], acc[mt][nt][1]);
                *(float2*)&C[(size_t)(r + 8) * N + c] =
                    make_float2(acc[mt][nt][2], acc[mt][nt][3]);
            }
        }
    }
}

// =================== RoPE + grouped scatter (fp16 in/out) ===================
__global__ __launch_bounds__(256) void rope_k(
    const float* __restrict__ fcos, const float* __restrict__ fsin)
{
    unsigned id = blockIdx.x * 256u + threadIdx.x;
    int j = id & 31;
    int t = (id >> 5) & (TT - 1);
    int h = (id >> 17) & (HH - 1);
    int b = id >> 21;
    const __half* row = g_qkvh + (size_t)(b * TT + t) * (3 * CC);
    float2 qv = __half22float2(*(const __half2*)(row + h * HSD + 2 * j));
    float2 kv = __half22float2(*(const __half2*)(row + CC + h * HSD + 2 * j));
    float2 vv = __half22float2(*(const __half2*)(row + 2 * CC + h * HSD + 2 * j));
    float c = fcos[t * 32 + j];
    float s = fsin[t * 32 + j];
    float2 qo = make_float2(qv.x * c - qv.y * s, qv.x * s + qv.y * c);
    float2 ko = make_float2(kv.x * c - kv.y * s, kv.x * s + kv.y * c);
    int h2 = t & 15;
    int gq = h >> 1;
    int gtq = ((h & 1) << 8) | (t >> 4);
    size_t qidx = (((size_t)((b * HH + h2) * GG + gq) * GTT + gtq) * HSD) + 2 * j;
    *(uint32_t*)(g_qh + qidx) = packh(qo.x, qo.y);
    *(uint32_t*)(g_kh + qidx) = packh(ko.x, ko.y);
    int gv = t >> 9, gtv = t & 511;
    size_t vidx = (((size_t)((b * HH + h) * GG + gv) * GTT + gtv) * HSD) + 2 * j;
    *(uint32_t*)(g_vh + vidx) = packh(vv.x, vv.y);
}

// =================== tensor-core block-causal flash attention ===================
// q-tile 64 rows (4 warps x 16), k-tile 128 cols. 3 K/V buffers (32KB each)
// + Q (8KB) = 104KB; 2 CTAs/SM; one barrier per k-tile.
#define ATT_SMEM 106496
#define ATT_QOFF 98304

__global__ __launch_bounds__(128, 2) void attn_k() {
    extern __shared__ __align__(16) char smraw[];
    uint32_t smb = (uint32_t)__cvta_generic_to_shared(smraw);
    int tid = threadIdx.x, lane = tid & 31, w = tid >> 5;
    int bx = blockIdx.x;
    int qt = 7 - (bx & 7);          // heavy tiles first
    int g  = (bx >> 3) & 7;
    int h  = (bx >> 6) & 15;
    int b  = bx >> 10;
    size_t gb = ((size_t)((b * HH + h) * GG + g)) * GTT * HSD;
    const __half* Qhp = g_qh + gb + (size_t)(64 * qt) * HSD;
    const __half* arrp[2] = { g_kh + gb, g_vh + gb };

    // stage Q (64x64 fp16 = 8KB)
    #pragma unroll
    for (int it = 0; it < 4; it++) {
        int cid = tid + it * 128;
        int r = cid >> 3, c = cid & 7;
        cp16s(smb + ATT_QOFF + swz(r, c), Qhp + r * HSD + c * 8);
    }
    asm volatile("cp.async.commit_group;" ::: "memory");
    asm volatile("cp.async.wait_group 0;" ::: "memory");
    __syncthreads();

    uint32_t qhf[4][4];
    int rq = w * 16;
    int sub = lane >> 3;
    #pragma unroll
    for (int kk = 0; kk < 4; kk++) {
        int r = rq + (sub & 1) * 8 + (lane & 7);
        int c = 2 * kk + (sub >> 1);
        ldsm4(qhf[kk], smb + ATT_QOFF + swz(r, c));
    }
    __syncthreads();

    int ntiles = (qt >> 1) + 1;

    // K/V tile (128x64 each): buffer buf at smb + buf*32768 (K +0, V +16384)
    auto load_kv = [&](int kt, int buf) {
        #pragma unroll
        for (int it = 0; it < 16; it++) {
            int cid = tid + it * 128;
            int arr = cid >> 10;
            int rc = cid & 1023;
            int r = rc >> 3, c = rc & 7;
            cp16s(smb + buf * 32768 + arr * 16384 + swz(r, c),
                  arrp[arr] + (size_t)(kt * 128 + r) * HSD + c * 8);
        }
        asm volatile("cp.async.commit_group;" ::: "memory");
    };

    load_kv(0, 0);
    if (ntiles > 1) load_kv(1, 1);

    float oacc[8][4] = {};
    float m_lo = -1e30f, m_hi = -1e30f, l_lo = 0.f, l_hi = 0.f;
    int scur = 0, snx2 = 2;

    for (int kt = 0; kt < ntiles; kt++) {
        if (kt + 1 < ntiles)
            asm volatile("cp.async.wait_group 1;" ::: "memory");
        else
            asm volatile("cp.async.wait_group 0;" ::: "memory");
        __syncthreads();
        if (kt + 2 < ntiles) load_kv(kt + 2, snx2);
        uint32_t kb0 = smb + scur * 32768;

        // ---- S = Q K^T : 64q x 128k ----
        float sacc[16][4] = {};
        #pragma unroll
        for (int kk = 0; kk < 4; kk++) {
            #pragma unroll
            for (int tp = 0; tp < 8; tp++) {
                uint32_t kh4[4];
                int r = tp * 16 + (sub >> 1) * 8 + (lane & 7);
                int c = 2 * kk + (sub & 1);
                ldsm4(kh4, kb0 + swz(r, c));
                mma_f16(sacc[2 * tp],     qhf[kk], kh4);
                mma_f16(sacc[2 * tp + 1], qhf[kk], kh4 + 2);
            }
        }

        int rowl = 64 * qt + w * 16 + (lane >> 2);
        bool nm = (kt * 128 + 127) > (64 * qt + w * 16);
        #pragma unroll
        for (int t = 0; t < 16; t++) {
            #pragma unroll
            for (int e = 0; e < 4; e++) {
                float s = sacc[t][e] * 0.125f;
                if (nm) {
                    int col = kt * 128 + t * 8 + ((lane & 3) << 1) + (e & 1);
                    int row = rowl + ((e & 2) ? 8 : 0);
                    if (col > row) s = -1e30f;
                }
                sacc[t][e] = s;
            }
        }

        float mlo = -1e30f, mhi = -1e30f;
        #pragma unroll
        for (int t = 0; t < 16; t++) {
            mlo = fmaxf(mlo, fmaxf(sacc[t][0], sacc[t][1]));
            mhi = fmaxf(mhi, fmaxf(sacc[t][2], sacc[t][3]));
        }
        mlo = fmaxf(mlo, __shfl_xor_sync(0xffffffffu, mlo, 1));
        mlo = fmaxf(mlo, __shfl_xor_sync(0xffffffffu, mlo, 2));
        mhi = fmaxf(mhi, __shfl_xor_sync(0xffffffffu, mhi, 1));
        mhi = fmaxf(mhi, __shfl_xor_sync(0xffffffffu, mhi, 2));
        float nmlo = fmaxf(m_lo, mlo), nmhi = fmaxf(m_hi, mhi);
        float clo = __expf(m_lo - nmlo), chi = __expf(m_hi - nmhi);
        m_lo = nmlo; m_hi = nmhi;
        float slo = 0.f, shi = 0.f;
        #pragma unroll
        for (int t = 0; t < 16; t++) {
            float p0 = __expf(sacc[t][0] - nmlo);
            float p1 = __expf(sacc[t][1] - nmlo);
            float p2 = __expf(sacc[t][2] - nmhi);
            float p3 = __expf(sacc[t][3] - nmhi);
            sacc[t][0] = p0; sacc[t][1] = p1; sacc[t][2] = p2; sacc[t][3] = p3;
            slo += p0 + p1; shi += p2 + p3;
        }
        slo += __shfl_xor_sync(0xffffffffu, slo, 1);
        slo += __shfl_xor_sync(0xffffffffu, slo, 2);
        shi += __shfl_xor_sync(0xffffffffu, shi, 1);
        shi += __shfl_xor_sync(0xffffffffu, shi, 2);
        l_lo = l_lo * clo + slo;
        l_hi = l_hi * chi + shi;
        #pragma unroll
        for (int t = 0; t < 8; t++) {
            oacc[t][0] *= clo; oacc[t][1] *= clo;
            oacc[t][2] *= chi; oacc[t][3] *= chi;
        }

        // ---- O += P V : P 64x128, V 128x64 ----
        #pragma unroll
        for (int jk = 0; jk < 8; jk++) {
            uint32_t aph[4];
            {
                int t0 = 2 * jk, t1 = t0 + 1;
                aph[0] = packh(sacc[t0][0], sacc[t0][1]);
                aph[1] = packh(sacc[t0][2], sacc[t0][3]);
                aph[2] = packh(sacc[t1][0], sacc[t1][1]);
                aph[3] = packh(sacc[t1][2], sacc[t1][3]);
            }
            #pragma unroll
            for (int dp = 0; dp < 4; dp++) {
                uint32_t vh4[4];
                int r = jk * 16 + (sub & 1) * 8 + (lane & 7);
                int c = 2 * dp + (sub >> 1);
                ldsm4t4(vh4, kb0 + 16384 + swz(r, c));
                mma_f16(oacc[2 * dp],     aph, vh4);
                mma_f16(oacc[2 * dp + 1], aph, vh4 + 2);
            }
        }
        scur = (scur == 2) ? 0 : scur + 1;
        snx2 = (snx2 == 2) ? 0 : snx2 + 1;
    }

    float ilo = 1.0f / l_lo, ihi = 1.0f / l_hi;
    size_t tau = (size_t)b * TT + g * GTT + 64 * qt + w * 16 + (lane >> 2);
    int colb = h * HSD + ((lane & 3) << 1);
    #pragma unroll
    for (int t = 0; t < 8; t++) {
        float v0 = oacc[t][0] * ilo, v1 = oacc[t][1] * ilo;
        float v2 = oacc[t][2] * ihi, v3 = oacc[t][3] * ihi;
        size_t o0 = tau * CC + colb + t * 8;
        size_t o1 = (tau + 8) * CC + colb + t * 8;
        *(uint32_t*)(g_obh + o0) = packh(v0, v1);
        *(uint32_t*)(g_obh + o1) = packh(v2, v3);
    }
}

// =================== Pooling (qb/kb/vb; L=1 attention is identity) ===================
__global__ __launch_bounds__(64) void pool_k(
    const float* __restrict__ qp, const float* __restrict__ kp,
    const float* __restrict__ vp, float* __restrict__ out)
{
    int bx = blockIdx.x;
    int which = bx / 448;
    int rem = bx - which * 448;
    int g = rem % 7;
    int bh = rem / 7;
    size_t base = ((size_t)bh * GG + g) * GTT * HSD;
    const __half* sh = (which == 0 ? g_qh : (which == 1 ? g_kh : g_vh)) + base;
    const float* proj = (which == 0 ? qp : (which == 1 ? kp : vp));
    int hs = threadIdx.x;
    float acc = 0.f;
    #pragma unroll 8
    for (int t = 0; t < GTT; t++)
        acc = fmaf(__half2float(sh[(size_t)t * HSD + hs]), proj[t], acc);
    out[(size_t)BB * TT * CC + (size_t)which * (BB * HH * 7 * HSD)
        + (size_t)(bh * 7 + g) * HSD + hs] = acc;
}

// =================== launch ===================
extern "C" void kernel_launch(void* const* d_in, const int* in_sizes, int n_in,
                              void* d_out, int out_size) {
    (void)in_sizes; (void)n_in; (void)out_size;
    const float* x    = (const float*)d_in[0];
    const float* Wqkv = (const float*)d_in[1];
    const float* Wo   = (const float*)d_in[2];
    const float* qp   = (const float*)d_in[3];
    const float* kp   = (const float*)d_in[4];
    const float* vp   = (const float*)d_in[5];
    const float* fc   = (const float*)d_in[6];
    const float* fs   = (const float*)d_in[7];
    float* out = (float*)d_out;

    __half *qkvh, *xh, *wqh, *woh, *obh;
    cudaGetSymbolAddress((void**)&qkvh, g_qkvh);
    cudaGetSymbolAddress((void**)&xh, g_xh);
    cudaGetSymbolAddress((void**)&wqh, g_wqh);
    cudaGetSymbolAddress((void**)&woh, g_woh);
    cudaGetSymbolAddress((void**)&obh, g_obh);

    cudaFuncSetAttribute(attn_k, cudaFuncAttributeMaxDynamicSharedMemorySize,
                         ATT_SMEM);
    cudaFuncSetAttribute(gemm1c_k<0>, cudaFuncAttributeMaxDynamicSharedMemorySize,
                         GEMM_SMEM);
    cudaFuncSetAttribute(gemm1c_k<1>, cudaFuncAttributeMaxDynamicSharedMemorySize,
                         GEMM_SMEM);

    // 0) convert operands to fp16
    int nx = BB * TT * CC;
    convh_k<<<(nx / 4 + 255) / 256, 256>>>(x, xh, nx);
    int nwq = CC * 3 * CC;
    convh_k<<<(nwq / 4 + 255) / 256, 256>>>(Wqkv, wqh, nwq);
    int nwo = CC * CC;
    convh_k<<<(nwo / 4 + 255) / 256, 256>>>(Wo, woh, nwo);

    // 1) qkv = x @ Wqkv  (single-pass fp16, fp16 output)
    dim3 g1(3 * CC / 128, BB * TT / 128);
    gemm1c_k<1><<<g1, 128, GEMM_SMEM>>>(xh, wqh, nullptr, qkvh,
                                        BB * TT, 3 * CC, CC);
    // 2) rope + grouped scatter (fp16)
    rope_k<<<(BB * HH * TT * 32) / 256, 256>>>(fc, fs);
    // 3) attention: 64q x 128k tiles, 4 warps, 2 CTAs/SM
    attn_k<<<BB * HH * GG * 8, 128, ATT_SMEM>>>();
    // 4) qb/kb/vb pools (tail of d_out)
    pool_k<<<3 * BB * HH * 7, 64>>>(qp, kp, vp, out);
    // 5) out = o @ Wo (fp32 output)
    dim3 g2(CC / 128, BB * TT / 128);
    gemm1c_k<0><<<g2, 128, GEMM_SMEM>>>(obh, woh, out, nullptr,
                                        BB * TT, CC, CC);
}